// round 5
// baseline (speedup 1.0000x reference)
#include <cuda_runtime.h>
#include <math.h>

#define MM   2049        // mesh points
#define NK   1025        // kappa = 0..1024 (Hermitian half)
#define NB   16          // batch
#define NPT  1024        // points per batch

// ---- f32-faithful constants (match jax weak-type promotion to float32) ----
#define C2PL_F   ((float)(2.0 * M_PI / 10.0))          // 2*pi/L as f32
#define FT32_F   ((float)(4.0 * 2.821e-5))             // 4*tau as f32
#define WIN_R    0.1090f                                // support radius (rad); arg>104 -> exp ~ 0
#define WJ       38                                     // window half-width in bins

// ---- scratch (device globals; no allocation allowed) ----
__device__ double g_gsum[NB * MM];
__device__ double g_Fre [NB * NK];
__device__ double g_Fim [NB * NK];
__device__ double g_D   [2  * NK];
__device__ double g_H   [NB * 2 * MM];
__device__ double g_Tc  [MM];
__device__ double g_Ts  [MM];
__device__ float  g_xg32[MM];

// XGRID computed exactly as numpy: ((2*pi) * (i * (10/2049))) / 10, f64 then cast f32
__device__ __forceinline__ float xgrid_f32(int m) {
    double v = (double)m * (10.0 / 2049.0);
    v = (6.283185307179586 * v) / 10.0;
    return (float)v;
}

// ============================================================================
// K_init: trig tables, xgrid table, zero gsum, Fourier multipliers D_c(kappa)
// ============================================================================
__global__ void k_init(const float* __restrict__ sh0, const float* __restrict__ am0,
                       const float* __restrict__ sh1, const float* __restrict__ am1) {
    int i = blockIdx.x * blockDim.x + threadIdx.x;
    if (i < MM) {
        double th = (6.283185307179586 * (double)i) / 2049.0;
        double s, c;
        sincos(th, &s, &c);
        g_Tc[i] = c;
        g_Ts[i] = s;
        g_xg32[i] = xgrid_f32(i);
    }
    if (i < NB * MM) g_gsum[i] = 0.0;
    if (i < NK) {
        double tau = (double)((float)2.821e-5);           // f32-rounded tau (as jax uses)
        double k2  = (double)i * (double)i;
        double dec2 = (M_PI / tau) * exp(2.0 * k2 * tau); // deconv^2
        double lo2p = 10.0 / (2.0 * M_PI);                // L/(2*pi)
        double s0 = 5.0 * (double)sh0[0];
        double s1 = 5.0 * (double)sh1[0];
        double m1 = -(double)am0[0] * 4.0 * M_PI / (k2 + s0 * s0);
        double den = k2 + s1 * s1;
        double m2 =  (double)am1[0] * 4.0 * M_PI / (den * den);
        g_D[i]      = lo2p * dec2 * m1;
        g_D[NK + i] = lo2p * dec2 * m2;
    }
}

// ============================================================================
// K_spread: gsum[b][m] = sum_n exp(-((x_n*c - xg_m)^2)/(4 tau))
// thread-per-bin, fixed n order -> deterministic, no atomics.
// f32 ops for diff/square/divide replicate the reference's f32 rounding.
// ============================================================================
__global__ __launch_bounds__(512) void k_spread(const float* __restrict__ x) {
    __shared__ float sx[NPT];
    int b = blockIdx.x;
    for (int n = threadIdx.x; n < NPT; n += blockDim.x)
        sx[n] = __fmul_rn(x[b * NPT + n], C2PL_F);
    __syncthreads();

    for (int m = blockIdx.y * 512 + threadIdx.x; m < MM; m += 2048) {
        float xg = g_xg32[m];
        double acc = 0.0;
        #pragma unroll 4
        for (int n = 0; n < NPT; ++n) {
            float t = __fsub_rn(sx[n], xg);
            if (fabsf(t) < WIN_R) {
                float arg = __fdiv_rn(__fmul_rn(t, t), FT32_F);
                acc += exp(-(double)arg);
            }
        }
        g_gsum[b * MM + m] = acc;
    }
}

// ============================================================================
// K_F: F_b(kappa) = sum_m gsum[b][m] * e^{-2 pi i kappa m / M}, kappa=0..1024
// warp per (b,kappa); incremental (kappa*m mod M) index into smem trig tables.
// ============================================================================
__global__ __launch_bounds__(256) void k_fourier() {
    __shared__ double sc[MM], ss[MM];
    for (int i = threadIdx.x; i < MM; i += 256) { sc[i] = g_Tc[i]; ss[i] = g_Ts[i]; }
    __syncthreads();

    int w    = threadIdx.x >> 5;
    int lane = threadIdx.x & 31;
    int wid  = blockIdx.x * 8 + w;
    if (wid >= NB * NK) return;
    int b = wid / NK;
    int k = wid % NK;

    int t   = (k * lane) % MM;
    int stp = (k * 32) % MM;
    double are = 0.0, aim = 0.0;
    for (int m = lane; m < MM; m += 32) {
        double gv = g_gsum[b * MM + m];
        are = fma(gv, sc[t], are);
        aim = fma(gv, ss[t], aim);
        t += stp; if (t >= MM) t -= MM;
    }
    #pragma unroll
    for (int o = 16; o > 0; o >>= 1) {
        are += __shfl_down_sync(0xffffffffu, are, o);
        aim += __shfl_down_sync(0xffffffffu, aim, o);
    }
    if (lane == 0) {
        g_Fre[b * NK + k] = are;
        g_Fim[b * NK + k] = -aim;   // e^{-i theta}
    }
}

// ============================================================================
// K_H: H[b,c][m] = (1/M) * ( D0*F0 + 2*sum_{k=1..1024} D(k)*Re(F(k) e^{+i th}) )
// warp per (b,c,m).
// ============================================================================
__global__ __launch_bounds__(256) void k_synth() {
    __shared__ double sc[MM], ss[MM];
    for (int i = threadIdx.x; i < MM; i += 256) { sc[i] = g_Tc[i]; ss[i] = g_Ts[i]; }
    __syncthreads();

    int w    = threadIdx.x >> 5;
    int lane = threadIdx.x & 31;
    int wid  = blockIdx.x * 8 + w;
    if (wid >= NB * 2 * MM) return;
    int bc = wid / MM;          // b*2 + c
    int m  = wid % MM;
    int b  = bc >> 1;
    int c  = bc & 1;

    int t   = (m * lane) % MM;
    int stp = (m * 32) % MM;
    double acc = 0.0;
    for (int k = lane; k < NK; k += 32) {
        double fre = g_Fre[b * NK + k];
        double fim = g_Fim[b * NK + k];
        double u = fma(fre, sc[t], -(fim * ss[t]));  // Re(F e^{+i th})
        acc = fma(g_D[c * NK + k], u, acc);
        t += stp; if (t >= MM) t -= MM;
    }
    #pragma unroll
    for (int o = 16; o > 0; o >>= 1)
        acc += __shfl_down_sync(0xffffffffu, acc, o);
    if (lane == 0) {
        double h = (2.0 * acc - g_D[c * NK] * g_Fre[b * NK]) / 2049.0;
        g_H[bc * MM + m] = h;
    }
}

// ============================================================================
// K_out: fmm[b,n,c] = (1/M) * sum_{m in window} g[b,n,m] * H[b,c][m]
// thread per point; f64 accumulation (H ~ 1e13 with near-Nyquist cancellation).
// ============================================================================
__global__ __launch_bounds__(256) void k_out(const float* __restrict__ x,
                                             float* __restrict__ out) {
    int gid = blockIdx.x * blockDim.x + threadIdx.x;
    if (gid >= NB * NPT) return;
    int b = gid / NPT;

    float xs = __fmul_rn(x[gid], C2PL_F);
    int cen = __float2int_rn(xs * (float)(2049.0 / (2.0 * M_PI)));

    const double* H0 = &g_H[(b * 2 + 0) * MM];
    const double* H1 = &g_H[(b * 2 + 1) * MM];

    double a0 = 0.0, a1 = 0.0;
    #pragma unroll 4
    for (int j = -WJ; j <= WJ; ++j) {
        int m = cen + j;
        if (m < 0 || m >= MM) continue;
        float t = __fsub_rn(xs, g_xg32[m]);
        if (fabsf(t) < WIN_R) {
            float arg = __fdiv_rn(__fmul_rn(t, t), FT32_F);
            double gv = exp(-(double)arg);
            a0 = fma(gv, H0[m], a0);
            a1 = fma(gv, H1[m], a1);
        }
    }
    out[gid * 2 + 0] = (float)(a0 / 2049.0);
    out[gid * 2 + 1] = (float)(a1 / 2049.0);
}

// ============================================================================
extern "C" void kernel_launch(void* const* d_in, const int* in_sizes, int n_in,
                              void* d_out, int out_size) {
    const float* x   = (const float*)d_in[0];
    const float* sh0 = (const float*)d_in[1];
    const float* am0 = (const float*)d_in[2];
    const float* sh1 = (const float*)d_in[3];
    const float* am1 = (const float*)d_in[4];
    float* out = (float*)d_out;

    // init: tables + D + zero gsum  (needs NB*MM threads)
    k_init<<<(NB * MM + 255) / 256, 256>>>(sh0, am0, sh1, am1);

    // spread: 16 batches x 4 bin-chunks
    dim3 gs(NB, 4);
    k_spread<<<gs, 512>>>(x);

    // forward transform: 16*1025 warps, 8 warps/block
    k_fourier<<<(NB * NK + 7) / 8, 256>>>();

    // inverse synthesis: 16*2*2049 warps, 8 warps/block
    k_synth<<<(NB * 2 * MM + 7) / 8, 256>>>();

    // interpolate back to points
    k_out<<<(NB * NPT + 255) / 256, 256>>>(x, out);
}

// round 8
// speedup vs baseline: 5.3935x; 5.3935x over previous
#include <cuda_runtime.h>
#include <math.h>

#define MM    2049        // mesh points
#define NK    1025        // kappa = 0..1024 (Hermitian half)
#define NPAD  1056        // padded m-pair count (multiple of 32, >= 1025)
#define NB    16          // batch
#define NPT   1024        // points per batch
#define NJ    32          // (b,c) pairs: j = b*2 + c

// ---- f32-faithful constants ----
#define C2PL_F   ((float)(2.0 * M_PI / 10.0))          // 2*pi/L as f32
#define FT32_F   ((float)(4.0 * 2.821e-5))             // 4*tau as f32
#define WIN_R    0.1090f                                // support radius (rad)
#define WJ       39                                     // window half-width in bins

// ---- scratch (device globals; no allocation allowed) ----
__device__ float g_gsum[NB * MM];
__device__ float g_gp  [NB * NPAD];   // gsum[m] + gsum[M-m], m-pair index 0..1024, zero-padded
__device__ float g_gm  [NB * NPAD];   // gsum[m] - gsum[M-m]
__device__ float g_Are [NJ * NK];     // D_c(k) * Re F_b(k)
__device__ float g_Aim [NJ * NK];     // D_c(k) * Im F_b(k)
__device__ float g_H   [NJ * MM];
__device__ float g_D   [2  * NK];
__device__ float g_c   [MM];
__device__ float g_s   [MM];
__device__ float g_xg  [MM];

// XGRID exactly as numpy: v = i*(10/2049); xg = (2*pi*v)/10, f64 then cast f32
__device__ __forceinline__ float xgrid_f32(int m) {
    double v = (double)m * (10.0 / 2049.0);
    v = (6.283185307179586 * v) / 10.0;
    return (float)v;
}

// ============================================================================
// K_init: trig tables (f32), xgrid, Fourier multipliers D_c(kappa) (f32)
// ============================================================================
__global__ void k_init(const float* __restrict__ sh0, const float* __restrict__ am0,
                       const float* __restrict__ sh1, const float* __restrict__ am1) {
    int i = blockIdx.x * blockDim.x + threadIdx.x;
    if (i < MM) {
        double th = (6.283185307179586 * (double)i) / 2049.0;
        double s, c;
        sincos(th, &s, &c);
        g_c[i] = (float)c;
        g_s[i] = (float)s;
        g_xg[i] = xgrid_f32(i);
    }
    if (i < NK) {
        double tau = (double)((float)2.821e-5);
        double k2  = (double)i * (double)i;
        double dec2 = (M_PI / tau) * exp(2.0 * k2 * tau); // deconv^2
        double lo2p = 10.0 / (2.0 * M_PI);                // L/(2*pi)
        double s0 = 5.0 * (double)sh0[0];
        double s1 = 5.0 * (double)sh1[0];
        double m1 = -(double)am0[0] * 4.0 * M_PI / (k2 + s0 * s0);
        double den = k2 + s1 * s1;
        double m2 =  (double)am1[0] * 4.0 * M_PI / (den * den);
        g_D[i]      = (float)(lo2p * dec2 * m1);
        g_D[NK + i] = (float)(lo2p * dec2 * m2);
    }
}

// ============================================================================
// K_spread: gsum[b][m] = sum_n expf(-((x_n*c - xg_m)^2)/(4 tau))
// Tile of 128 bins per block; deterministic ordered candidate compaction
// (n-order preserved), then thread-per-bin f32 accumulation.
// ============================================================================
__global__ __launch_bounds__(128) void k_spread(const float* __restrict__ x) {
    __shared__ float cand[NPT];
    __shared__ int   warp_cnt[4];

    int b    = blockIdx.x;
    int tile = blockIdx.y;          // 0..16
    int lo   = tile * 128;
    int t    = threadIdx.x;
    int lane = t & 31, w = t >> 5;

    // Phase 1: each thread scans 8 consecutive points (preserves global n-order)
    const float* xb = x + b * NPT;
    float v[8];
    int flags = 0, cnt = 0;
    float fl = (float)(lo - 40), fh = (float)(lo + 127 + 40);
    #pragma unroll
    for (int i = 0; i < 8; ++i) {
        float xs = __fmul_rn(xb[t * 8 + i], C2PL_F);
        v[i] = xs;
        float cenf = xs * (float)(2049.0 / (2.0 * M_PI));
        int ok = (cenf >= fl) && (cenf <= fh);
        flags |= ok << i;
        cnt += ok;
    }
    // ordered block-wide exclusive scan of per-thread counts
    int inc = cnt;
    #pragma unroll
    for (int o = 1; o < 32; o <<= 1) {
        int z = __shfl_up_sync(0xffffffffu, inc, o);
        if (lane >= o) inc += z;
    }
    if (lane == 31) warp_cnt[w] = inc;
    __syncthreads();
    int woff = 0;
    for (int i = 0; i < w; ++i) woff += warp_cnt[i];
    int ntot = warp_cnt[0] + warp_cnt[1] + warp_cnt[2] + warp_cnt[3];
    int off = woff + inc - cnt;     // exclusive offset for this thread
    #pragma unroll
    for (int i = 0; i < 8; ++i)
        if ((flags >> i) & 1) cand[off++] = v[i];
    __syncthreads();

    // Phase 2: one thread per bin
    int m = lo + t;
    if (m < MM) {
        float xg = g_xg[m];
        float acc = 0.0f;
        for (int i = 0; i < ntot; ++i) {
            float d = __fsub_rn(cand[i], xg);
            if (fabsf(d) < WIN_R) {
                float arg = __fdiv_rn(__fmul_rn(d, d), FT32_F);
                acc += expf(-arg);
            }
        }
        g_gsum[b * MM + m] = acc;
    }
}

// ============================================================================
// K_prep: sum/diff fold  gp[mp]=g[mp]+g[M-mp], gm[mp]=g[mp]-g[M-mp]; mp=0 -> g[0]
// ============================================================================
__global__ void k_prep() {
    int i = blockIdx.x * blockDim.x + threadIdx.x;
    if (i >= NB * NPAD) return;
    int b = i / NPAD, mp = i % NPAD;
    float gp = 0.0f, gm = 0.0f;
    if (mp == 0) {
        gp = g_gsum[b * MM];
    } else if (mp <= 1024) {
        float a = g_gsum[b * MM + mp];
        float c = g_gsum[b * MM + 2049 - mp];
        gp = a + c;
        gm = a - c;
    }
    g_gp[i] = gp;
    g_gm[i] = gm;
}

// ============================================================================
// K_fourier: F_b(k) = gp.cos - i*gm.sin over m-pairs; warp per (k, 4-batch group);
// epilogue folds D: A[j][k] = D_c(k) * F_b(k), j = b*2+c.
// ============================================================================
__global__ __launch_bounds__(256) void k_fourier() {
    __shared__ float sc[MM], ss[MM];
    for (int i = threadIdx.x; i < MM; i += 256) { sc[i] = g_c[i]; ss[i] = g_s[i]; }
    __syncthreads();

    int w    = (blockIdx.x * 256 + threadIdx.x) >> 5;
    int lane = threadIdx.x & 31;
    if (w >= NK * 4) return;
    int k  = w >> 2;
    int b0 = (w & 3) * 4;

    int t   = (k * lane) % MM;
    int stp = (k * 32) % MM;
    float fr0 = 0.f, fi0 = 0.f, fr1 = 0.f, fi1 = 0.f;
    float fr2 = 0.f, fi2 = 0.f, fr3 = 0.f, fi3 = 0.f;

    int mp = lane;
    #pragma unroll 1
    for (int it = 0; it < 33; ++it) {       // covers mp = 0..1055 (padded)
        float c = sc[t], s = ss[t];
        fr0 = fmaf(g_gp[(b0 + 0) * NPAD + mp], c, fr0);
        fi0 = fmaf(g_gm[(b0 + 0) * NPAD + mp], s, fi0);
        fr1 = fmaf(g_gp[(b0 + 1) * NPAD + mp], c, fr1);
        fi1 = fmaf(g_gm[(b0 + 1) * NPAD + mp], s, fi1);
        fr2 = fmaf(g_gp[(b0 + 2) * NPAD + mp], c, fr2);
        fi2 = fmaf(g_gm[(b0 + 2) * NPAD + mp], s, fi2);
        fr3 = fmaf(g_gp[(b0 + 3) * NPAD + mp], c, fr3);
        fi3 = fmaf(g_gm[(b0 + 3) * NPAD + mp], s, fi3);
        mp += 32;
        t += stp; if (t >= MM) t -= MM;
    }
    #pragma unroll
    for (int o = 16; o > 0; o >>= 1) {
        fr0 += __shfl_down_sync(0xffffffffu, fr0, o);
        fi0 += __shfl_down_sync(0xffffffffu, fi0, o);
        fr1 += __shfl_down_sync(0xffffffffu, fr1, o);
        fi1 += __shfl_down_sync(0xffffffffu, fi1, o);
        fr2 += __shfl_down_sync(0xffffffffu, fr2, o);
        fi2 += __shfl_down_sync(0xffffffffu, fi2, o);
        fr3 += __shfl_down_sync(0xffffffffu, fr3, o);
        fi3 += __shfl_down_sync(0xffffffffu, fi3, o);
    }
    if (lane == 0) {
        float D0 = g_D[k], D1 = g_D[NK + k];
        float fre[4] = {fr0, fr1, fr2, fr3};
        float fim[4] = {-fi0, -fi1, -fi2, -fi3};
        #pragma unroll
        for (int i = 0; i < 4; ++i) {
            int j0 = (b0 + i) * 2;
            g_Are[(j0 + 0) * NK + k] = D0 * fre[i];
            g_Aim[(j0 + 0) * NK + k] = D0 * fim[i];
            g_Are[(j0 + 1) * NK + k] = D1 * fre[i];
            g_Aim[(j0 + 1) * NK + k] = D1 * fim[i];
        }
    }
}

// ============================================================================
// K_synth: U = sum_k Are.cos(k th_m), V = sum_k Aim.sin(k th_m), k=1..1024;
// H[m] = (A0 + 2(U - V))/M, H[M-m] = (A0 + 2(U + V))/M.
// Warp per (m-pair, 4-j group), lanes over k.
// ============================================================================
__global__ __launch_bounds__(256) void k_synth() {
    __shared__ float sc[MM], ss[MM];
    for (int i = threadIdx.x; i < MM; i += 256) { sc[i] = g_c[i]; ss[i] = g_s[i]; }
    __syncthreads();

    int w    = (blockIdx.x * 256 + threadIdx.x) >> 5;
    int lane = threadIdx.x & 31;
    if (w >= NK * 8) return;
    int mp = w >> 3;                // 0..1024
    int j0 = (w & 7) * 4;

    int t   = (mp * (1 + lane)) % MM;
    int stp = (32 * mp) % MM;
    float U0 = 0.f, V0 = 0.f, U1 = 0.f, V1 = 0.f;
    float U2 = 0.f, V2 = 0.f, U3 = 0.f, V3 = 0.f;

    const float* A0r = g_Are + (j0 + 0) * NK;
    const float* A0i = g_Aim + (j0 + 0) * NK;
    const float* A1r = g_Are + (j0 + 1) * NK;
    const float* A1i = g_Aim + (j0 + 1) * NK;
    const float* A2r = g_Are + (j0 + 2) * NK;
    const float* A2i = g_Aim + (j0 + 2) * NK;
    const float* A3r = g_Are + (j0 + 3) * NK;
    const float* A3i = g_Aim + (j0 + 3) * NK;

    int k = 1 + lane;
    #pragma unroll 1
    for (int it = 0; it < 32; ++it) {       // k = 1..1024
        float c = sc[t], s = ss[t];
        U0 = fmaf(A0r[k], c, U0);
        V0 = fmaf(A0i[k], s, V0);
        U1 = fmaf(A1r[k], c, U1);
        V1 = fmaf(A1i[k], s, V1);
        U2 = fmaf(A2r[k], c, U2);
        V2 = fmaf(A2i[k], s, V2);
        U3 = fmaf(A3r[k], c, U3);
        V3 = fmaf(A3i[k], s, V3);
        k += 32;
        t += stp; if (t >= MM) t -= MM;
    }
    #pragma unroll
    for (int o = 16; o > 0; o >>= 1) {
        U0 += __shfl_down_sync(0xffffffffu, U0, o);
        V0 += __shfl_down_sync(0xffffffffu, V0, o);
        U1 += __shfl_down_sync(0xffffffffu, U1, o);
        V1 += __shfl_down_sync(0xffffffffu, V1, o);
        U2 += __shfl_down_sync(0xffffffffu, U2, o);
        V2 += __shfl_down_sync(0xffffffffu, V2, o);
        U3 += __shfl_down_sync(0xffffffffu, U3, o);
        V3 += __shfl_down_sync(0xffffffffu, V3, o);
    }
    if (lane == 0) {
        const float inv = 1.0f / 2049.0f;
        float U[4] = {U0, U1, U2, U3};
        float V[4] = {V0, V1, V2, V3};
        #pragma unroll
        for (int i = 0; i < 4; ++i) {
            float a0 = g_Are[(j0 + i) * NK];     // k=0 term
            g_H[(j0 + i) * MM + mp] = (a0 + 2.0f * (U[i] - V[i])) * inv;
            if (mp)
                g_H[(j0 + i) * MM + 2049 - mp] = (a0 + 2.0f * (U[i] + V[i])) * inv;
        }
    }
}

// ============================================================================
// K_out: fmm[b,n,c] = (1/M) * sum_{m in window} g[b,n,m] * H[b,c][m]
// f32 H and expf; f64 accumulator (cheap, 2.5M DFMA).
// ============================================================================
__global__ __launch_bounds__(256) void k_out(const float* __restrict__ x,
                                             float* __restrict__ out) {
    int gid = blockIdx.x * blockDim.x + threadIdx.x;
    if (gid >= NB * NPT) return;
    int b = gid / NPT;

    float xs = __fmul_rn(x[gid], C2PL_F);
    int cen = __float2int_rn(xs * (float)(2049.0 / (2.0 * M_PI)));

    const float* H0 = g_H + (2 * b + 0) * MM;
    const float* H1 = g_H + (2 * b + 1) * MM;

    double a0 = 0.0, a1 = 0.0;
    #pragma unroll 4
    for (int j = -WJ; j <= WJ; ++j) {
        int m = cen + j;
        if (m < 0 || m >= MM) continue;
        float d = __fsub_rn(xs, g_xg[m]);
        if (fabsf(d) < WIN_R) {
            float arg = __fdiv_rn(__fmul_rn(d, d), FT32_F);
            double gv = (double)expf(-arg);
            a0 = fma(gv, (double)H0[m], a0);
            a1 = fma(gv, (double)H1[m], a1);
        }
    }
    out[gid * 2 + 0] = (float)(a0 / 2049.0);
    out[gid * 2 + 1] = (float)(a1 / 2049.0);
}

// ============================================================================
extern "C" void kernel_launch(void* const* d_in, const int* in_sizes, int n_in,
                              void* d_out, int out_size) {
    const float* x   = (const float*)d_in[0];
    const float* sh0 = (const float*)d_in[1];
    const float* am0 = (const float*)d_in[2];
    const float* sh1 = (const float*)d_in[3];
    const float* am1 = (const float*)d_in[4];
    float* out = (float*)d_out;

    // tables + multipliers
    k_init<<<(MM + 255) / 256, 256>>>(sh0, am0, sh1, am1);

    // spread: 16 batches x 17 tiles of 128 bins
    dim3 gs(NB, 17);
    k_spread<<<gs, 128>>>(x);

    // sum/diff fold
    k_prep<<<(NB * NPAD + 255) / 256, 256>>>();

    // forward transform + D fold: 1025*4 warps, 8 warps/block
    k_fourier<<<(NK * 4 + 7) / 8, 256>>>();

    // inverse synthesis: 1025*8 warps, 8 warps/block
    k_synth<<<NK, 256>>>();

    // interpolate back to points
    k_out<<<(NB * NPT + 255) / 256, 256>>>(x, out);
}

// round 9
// speedup vs baseline: 8.7228x; 1.6173x over previous
#include <cuda_runtime.h>
#include <math.h>

#define MM    2049        // mesh points
#define NK    1025        // kappa = 0..1024 (Hermitian half)
#define NPAD  1152        // padded m-pair count (9 chunks of 128)
#define NB    16          // batch
#define NPT   1024        // points per batch
#define NJ    32          // (b,c) pairs: j = b*2 + c

// ---- f32-faithful constants ----
#define C2PL_F   ((float)(2.0 * M_PI / 10.0))          // 2*pi/L as f32
#define FT32_F   ((float)(4.0 * 2.821e-5))             // 4*tau as f32
#define WIN_R    0.1090f                                // support radius (rad)
#define WJ       39                                     // window half-width in bins

// ---- scratch (device globals; no allocation allowed) ----
__device__ float  g_gsum[NB * MM];
__device__ float  g_gp  [NB * NPAD];   // gsum[m]+gsum[M-m], zero-padded
__device__ float  g_gm  [NB * NPAD];   // gsum[m]-gsum[M-m]
__device__ float  g_Are [NJ * 1024];   // D_c(k)*Re F_b(k), shifted: index k-1
__device__ float  g_Aim [NJ * 1024];   // D_c(k)*Im F_b(k), shifted: index k-1
__device__ float  g_A0  [NJ];          // k = 0 term
__device__ float2 g_H   [NB * MM];     // H packed {c0, c1} per (b, m)
__device__ float  g_D   [2  * NK];
__device__ float  g_c   [MM];
__device__ float  g_s   [MM];
__device__ float  g_xg  [MM];

// XGRID exactly as numpy: v = i*(10/2049); xg = (2*pi*v)/10, f64 then cast f32
__device__ __forceinline__ float xgrid_f32(int m) {
    double v = (double)m * (10.0 / 2049.0);
    v = (6.283185307179586 * v) / 10.0;
    return (float)v;
}

// ============================================================================
// K_init: trig tables (f32), xgrid, Fourier multipliers D_c(kappa) (f32)
// ============================================================================
__global__ void k_init(const float* __restrict__ sh0, const float* __restrict__ am0,
                       const float* __restrict__ sh1, const float* __restrict__ am1) {
    int i = blockIdx.x * blockDim.x + threadIdx.x;
    if (i < MM) {
        double th = (6.283185307179586 * (double)i) / 2049.0;
        double s, c;
        sincos(th, &s, &c);
        g_c[i] = (float)c;
        g_s[i] = (float)s;
        g_xg[i] = xgrid_f32(i);
    }
    if (i < NK) {
        double tau = (double)((float)2.821e-5);
        double k2  = (double)i * (double)i;
        double dec2 = (M_PI / tau) * exp(2.0 * k2 * tau); // deconv^2
        double lo2p = 10.0 / (2.0 * M_PI);                // L/(2*pi)
        double s0 = 5.0 * (double)sh0[0];
        double s1 = 5.0 * (double)sh1[0];
        double m1 = -(double)am0[0] * 4.0 * M_PI / (k2 + s0 * s0);
        double den = k2 + s1 * s1;
        double m2 =  (double)am1[0] * 4.0 * M_PI / (den * den);
        g_D[i]      = (float)(lo2p * dec2 * m1);
        g_D[NK + i] = (float)(lo2p * dec2 * m2);
    }
}

// ============================================================================
// K_spread: gsum[b][m] = sum_n expf(-((x_n*c - xg_m)^2)/(4 tau))
// Tile of 128 bins per block; deterministic ordered candidate compaction.
// ============================================================================
__global__ __launch_bounds__(128) void k_spread(const float* __restrict__ x) {
    __shared__ float cand[NPT];
    __shared__ int   warp_cnt[4];

    int b    = blockIdx.x;
    int tile = blockIdx.y;          // 0..16
    int lo   = tile * 128;
    int t    = threadIdx.x;
    int lane = t & 31, w = t >> 5;

    const float* xb = x + b * NPT;
    float v[8];
    int flags = 0, cnt = 0;
    float fl = (float)(lo - 40), fh = (float)(lo + 127 + 40);
    #pragma unroll
    for (int i = 0; i < 8; ++i) {
        float xs = __fmul_rn(xb[t * 8 + i], C2PL_F);
        v[i] = xs;
        float cenf = xs * (float)(2049.0 / (2.0 * M_PI));
        int ok = (cenf >= fl) && (cenf <= fh);
        flags |= ok << i;
        cnt += ok;
    }
    int inc = cnt;
    #pragma unroll
    for (int o = 1; o < 32; o <<= 1) {
        int z = __shfl_up_sync(0xffffffffu, inc, o);
        if (lane >= o) inc += z;
    }
    if (lane == 31) warp_cnt[w] = inc;
    __syncthreads();
    int woff = 0;
    for (int i = 0; i < w; ++i) woff += warp_cnt[i];
    int ntot = warp_cnt[0] + warp_cnt[1] + warp_cnt[2] + warp_cnt[3];
    int off = woff + inc - cnt;
    #pragma unroll
    for (int i = 0; i < 8; ++i)
        if ((flags >> i) & 1) cand[off++] = v[i];
    __syncthreads();

    int m = lo + t;
    if (m < MM) {
        float xg = g_xg[m];
        float acc = 0.0f;
        for (int i = 0; i < ntot; ++i) {
            float d = __fsub_rn(cand[i], xg);
            if (fabsf(d) < WIN_R) {
                float arg = __fdiv_rn(__fmul_rn(d, d), FT32_F);
                acc += expf(-arg);
            }
        }
        g_gsum[b * MM + m] = acc;
    }
}

// ============================================================================
// K_prep: gp[mp]=g[mp]+g[M-mp], gm[mp]=g[mp]-g[M-mp]; mp=0 -> g[0]; pad zeros.
// ============================================================================
__global__ void k_prep() {
    int i = blockIdx.x * blockDim.x + threadIdx.x;
    if (i >= NB * NPAD) return;
    int b = i / NPAD, mp = i % NPAD;
    float gp = 0.0f, gm = 0.0f;
    if (mp == 0) {
        gp = g_gsum[b * MM];
    } else if (mp <= 1024) {
        float a = g_gsum[b * MM + mp];
        float c = g_gsum[b * MM + 2049 - mp];
        gp = a + c;
        gm = a - c;
    }
    g_gp[i] = gp;
    g_gm[i] = gm;
}

// ============================================================================
// K_fourier: warp per (k, 8-batch group). Lane owns 4 consecutive mp ->
// LDG.128 operands; 64 FFMA per iteration vs ~34 other instructions.
// Epilogue folds D and writes shifted A layout.
// ============================================================================
__global__ __launch_bounds__(256) void k_fourier() {
    __shared__ float sc[MM], ss[MM];
    for (int i = threadIdx.x; i < MM; i += 256) { sc[i] = g_c[i]; ss[i] = g_s[i]; }
    __syncthreads();

    int w    = (blockIdx.x * 256 + threadIdx.x) >> 5;
    int lane = threadIdx.x & 31;
    if (w >= NK * 2) return;
    int k  = w >> 1;
    int b0 = (w & 1) * 8;

    int t   = (4 * lane * k) % MM;
    int stp = (128 * k) % MM;
    float fr[8], fi[8];
    #pragma unroll
    for (int i = 0; i < 8; ++i) { fr[i] = 0.0f; fi[i] = 0.0f; }

    int mp = lane * 4;
    #pragma unroll 1
    for (int it = 0; it < 9; ++it) {        // mp = 0..1151 (zero-padded)
        int u = t;
        float c0 = sc[u], s0 = ss[u]; u += k; if (u >= MM) u -= MM;
        float c1 = sc[u], s1 = ss[u]; u += k; if (u >= MM) u -= MM;
        float c2 = sc[u], s2 = ss[u]; u += k; if (u >= MM) u -= MM;
        float c3 = sc[u], s3 = ss[u];
        #pragma unroll
        for (int i = 0; i < 8; ++i) {
            float4 p = *(const float4*)&g_gp[(b0 + i) * NPAD + mp];
            float4 q = *(const float4*)&g_gm[(b0 + i) * NPAD + mp];
            fr[i] = fmaf(p.x, c0, fmaf(p.y, c1, fmaf(p.z, c2, fmaf(p.w, c3, fr[i]))));
            fi[i] = fmaf(q.x, s0, fmaf(q.y, s1, fmaf(q.z, s2, fmaf(q.w, s3, fi[i]))));
        }
        mp += 128;
        t += stp; if (t >= MM) t -= MM;
    }
    #pragma unroll
    for (int o = 16; o > 0; o >>= 1) {
        #pragma unroll
        for (int i = 0; i < 8; ++i) {
            fr[i] += __shfl_down_sync(0xffffffffu, fr[i], o);
            fi[i] += __shfl_down_sync(0xffffffffu, fi[i], o);
        }
    }
    if (lane == 0) {
        float D0 = g_D[k], D1 = g_D[NK + k];
        #pragma unroll
        for (int i = 0; i < 8; ++i) {
            int j0 = (b0 + i) * 2;
            float re =  fr[i];
            float im = -fi[i];
            if (k == 0) {
                g_A0[j0]     = D0 * re;
                g_A0[j0 + 1] = D1 * re;
            } else {
                g_Are[j0 * 1024 + k - 1]       = D0 * re;
                g_Aim[j0 * 1024 + k - 1]       = D0 * im;
                g_Are[(j0 + 1) * 1024 + k - 1] = D1 * re;
                g_Aim[(j0 + 1) * 1024 + k - 1] = D1 * im;
            }
        }
    }
}

// ============================================================================
// K_synth: warp per (m-pair, 8-j group = 4 batches x 2 channels).
// Lane owns 4 consecutive k -> LDG.128 on the shifted A arrays.
// H[m]=(A0+2(U-V))/M, H[M-m]=(A0+2(U+V))/M; packed float2 per (b,m).
// ============================================================================
__global__ __launch_bounds__(256) void k_synth() {
    __shared__ float sc[MM], ss[MM];
    for (int i = threadIdx.x; i < MM; i += 256) { sc[i] = g_c[i]; ss[i] = g_s[i]; }
    __syncthreads();

    int w    = (blockIdx.x * 256 + threadIdx.x) >> 5;
    int lane = threadIdx.x & 31;
    if (w >= NK * 4) return;
    int mp = w >> 2;                // 0..1024
    int b0 = (w & 3) * 4;           // 4 batches, both channels
    int j0 = b0 * 2;

    int t   = (mp * (1 + lane * 4)) % MM;   // theta index for k = 1 + 4*lane
    int stp = (128 * mp) % MM;
    float U[8], V[8];
    #pragma unroll
    for (int i = 0; i < 8; ++i) { U[i] = 0.0f; V[i] = 0.0f; }

    int kk = lane * 4;              // shifted index (k-1)
    #pragma unroll 1
    for (int it = 0; it < 8; ++it) {        // k = 1..1024
        int u = t;
        float c0 = sc[u], s0 = ss[u]; u += mp; if (u >= MM) u -= MM;
        float c1 = sc[u], s1 = ss[u]; u += mp; if (u >= MM) u -= MM;
        float c2 = sc[u], s2 = ss[u]; u += mp; if (u >= MM) u -= MM;
        float c3 = sc[u], s3 = ss[u];
        #pragma unroll
        for (int i = 0; i < 8; ++i) {
            float4 ar = *(const float4*)&g_Are[(j0 + i) * 1024 + kk];
            float4 ai = *(const float4*)&g_Aim[(j0 + i) * 1024 + kk];
            U[i] = fmaf(ar.x, c0, fmaf(ar.y, c1, fmaf(ar.z, c2, fmaf(ar.w, c3, U[i]))));
            V[i] = fmaf(ai.x, s0, fmaf(ai.y, s1, fmaf(ai.z, s2, fmaf(ai.w, s3, V[i]))));
        }
        kk += 128;
        t += stp; if (t >= MM) t -= MM;
    }
    #pragma unroll
    for (int o = 16; o > 0; o >>= 1) {
        #pragma unroll
        for (int i = 0; i < 8; ++i) {
            U[i] += __shfl_down_sync(0xffffffffu, U[i], o);
            V[i] += __shfl_down_sync(0xffffffffu, V[i], o);
        }
    }
    if (lane == 0) {
        const float inv = 1.0f / 2049.0f;
        #pragma unroll
        for (int bi = 0; bi < 4; ++bi) {
            int b  = b0 + bi;
            float a00 = g_A0[2 * b];
            float a01 = g_A0[2 * b + 1];
            float2 hm;
            hm.x = (a00 + 2.0f * (U[2 * bi]     - V[2 * bi]))     * inv;
            hm.y = (a01 + 2.0f * (U[2 * bi + 1] - V[2 * bi + 1])) * inv;
            g_H[b * MM + mp] = hm;
            if (mp) {
                float2 hp;
                hp.x = (a00 + 2.0f * (U[2 * bi]     + V[2 * bi]))     * inv;
                hp.y = (a01 + 2.0f * (U[2 * bi + 1] + V[2 * bi + 1])) * inv;
                g_H[b * MM + 2049 - mp] = hp;
            }
        }
    }
}

// ============================================================================
// K_out: fmm[b,n,c] = (1/M) * sum_{m in window} g[b,n,m] * H[b][m].c
// float2 H loads; f64 accumulator (cheap).
// ============================================================================
__global__ __launch_bounds__(256) void k_out(const float* __restrict__ x,
                                             float* __restrict__ out) {
    int gid = blockIdx.x * blockDim.x + threadIdx.x;
    if (gid >= NB * NPT) return;
    int b = gid / NPT;

    float xs = __fmul_rn(x[gid], C2PL_F);
    int cen = __float2int_rn(xs * (float)(2049.0 / (2.0 * M_PI)));

    const float2* Hb = g_H + b * MM;

    double a0 = 0.0, a1 = 0.0;
    #pragma unroll 4
    for (int j = -WJ; j <= WJ; ++j) {
        int m = cen + j;
        if (m < 0 || m >= MM) continue;
        float d = __fsub_rn(xs, g_xg[m]);
        if (fabsf(d) < WIN_R) {
            float arg = __fdiv_rn(__fmul_rn(d, d), FT32_F);
            double gv = (double)expf(-arg);
            float2 h = Hb[m];
            a0 = fma(gv, (double)h.x, a0);
            a1 = fma(gv, (double)h.y, a1);
        }
    }
    out[gid * 2 + 0] = (float)(a0 / 2049.0);
    out[gid * 2 + 1] = (float)(a1 / 2049.0);
}

// ============================================================================
extern "C" void kernel_launch(void* const* d_in, const int* in_sizes, int n_in,
                              void* d_out, int out_size) {
    const float* x   = (const float*)d_in[0];
    const float* sh0 = (const float*)d_in[1];
    const float* am0 = (const float*)d_in[2];
    const float* sh1 = (const float*)d_in[3];
    const float* am1 = (const float*)d_in[4];
    float* out = (float*)d_out;

    k_init<<<(MM + 255) / 256, 256>>>(sh0, am0, sh1, am1);

    dim3 gs(NB, 17);
    k_spread<<<gs, 128>>>(x);

    k_prep<<<(NB * NPAD + 255) / 256, 256>>>();

    // forward transform + D fold: NK*2 warps, 8 warps/block
    k_fourier<<<(NK * 2 + 7) / 8, 256>>>();

    // inverse synthesis: NK*4 warps, 8 warps/block
    k_synth<<<(NK * 4 + 7) / 8, 256>>>();

    k_out<<<(NB * NPT + 255) / 256, 256>>>(x, out);
}